// round 13
// baseline (speedup 1.0000x reference)
#include <cuda_runtime.h>
#include <math.h>

#define WIN   11
#define RAD   5
#define TSX   32
#define TSY   24
#define INWX  42              // TSX + 2*RAD
#define INWY  34              // TSY + 2*RAD
#define PAB   43              // packed (A,B) pitch in f2 units (odd -> CF row-walk LDS.64)
#define PF    45              // scalar F pitch in floats (odd -> CF)
#define PHB   71              // hb pitch in 16B units (odd -> CF row-walk stores)
#define HB1OFF 36             // second field-half offset, 36%8=4 -> CF split v-loads (R8-verified)
#define NTHREADS 256
#define GRIDY 22              // ceil(512/24)
#define NBLOCKS  (16 * GRIDY * 48)

#define C1 0.0001f
#define C2 0.0009f

struct GW { float g[WIN]; };

typedef unsigned long long f2_t;
__device__ __forceinline__ f2_t pack2(float lo, float hi) {
    f2_t r; asm("mov.b64 %0, {%1, %2};" : "=l"(r) : "f"(lo), "f"(hi)); return r;
}
__device__ __forceinline__ void unpack2(f2_t v, float& lo, float& hi) {
    asm("mov.b64 {%0, %1}, %2;" : "=f"(lo), "=f"(hi) : "l"(v));
}
__device__ __forceinline__ void fma2(f2_t& d, f2_t a, f2_t b) {
    asm("fma.rn.f32x2 %0, %1, %2, %0;" : "+l"(d) : "l"(a), "l"(b));
}
__device__ __forceinline__ f2_t mul2(f2_t a, f2_t b) {
    f2_t r; asm("mul.rn.f32x2 %0, %1, %2;" : "=l"(r) : "l"(a), "l"(b)); return r;
}

__device__ float        g_partials[NBLOCKS];
__device__ unsigned int g_done = 0;

// ---- shared layout (float units) ----
// sAB : f2  [34][43] = 2924 floats
// sF  : f32 [34][45] = 1530 floats
// hb  : ull2 rows pitch 71 (16B units); cols 0..33 = (AB,AABB), 36..69 = (AFBF,FFF)
#define OFF_F    2924
#define OFF_HB   4456                        // 16B aligned (4456*4 = 17824)
#define OFF_RED  (OFF_HB + INWY * PHB * 4)   // 4456 + 9656 = 14112
#define SMEM_FLOATS (OFF_RED + 16)
#define SMEM_BYTES  (SMEM_FLOATS * 4)        // 56512 B -> 4 CTAs/SM (226KB/228KB)

__device__ __forceinline__ float ssim_val(float mu1, float mu2,
                                          float e11, float e22, float e12) {
    float mu1sq = mu1 * mu1;
    float mu2sq = mu2 * mu2;
    float mu12  = mu1 * mu2;
    float num = (2.0f * mu12 + C1) * (2.0f * (e12 - mu12) + C2);
    float den = (mu1sq + mu2sq + C1) * ((e11 - mu1sq) + (e22 - mu2sq) + C2);
    return __fdividef(num, den);
}

// symmetric taps: g[k] == g[10-k]; k compile-time at every use
#define GSYM(k) gg[(k) < 6 ? (k) : 10 - (k)]

__global__ __launch_bounds__(NTHREADS, 4)
void ssim_tile_kernel(const float* __restrict__ A,
                      const float* __restrict__ B,
                      const float* __restrict__ F,
                      GW gw,
                      float* __restrict__ out) {
    extern __shared__ float sm[];
    f2_t*       sAB = (f2_t*)sm;
    float*      sF  = sm + OFF_F;
    ulonglong2* hb  = (ulonglong2*)(sm + OFF_HB);
    float*      red = sm + OFF_RED;

    const int tid = threadIdx.x;
    const int x0 = blockIdx.x * TSX - RAD;
    const int y0 = blockIdx.y * TSY - RAD;
    const size_t pbase = (size_t)blockIdx.z * (512 * 512);

    f2_t gg[6];
    #pragma unroll
    for (int k = 0; k < 6; k++) gg[k] = pack2(gw.g[k], gw.g[k]);

    // ---- stage raw: (A,B) packed + F scalar, zero-padded ----
    for (int i = tid; i < INWY * INWX; i += NTHREADS) {
        int r = i / INWX, c = i - r * INWX;
        int gx = x0 + c, gy = y0 + r;
        float a = 0.f, b = 0.f, f = 0.f;
        if ((unsigned)gx < 512u && (unsigned)gy < 512u) {
            size_t off = pbase + (size_t)gy * 512 + gx;
            a = A[off]; b = B[off]; f = F[off];
        }
        sAB[r * PAB + c] = pack2(a, b);
        sF[r * PF + c] = f;
    }
    __syncthreads();

    // ---- horizontal pass: 34 rows x 16 groups = 544 items, lanes walk rows ----
    for (int i = tid; i < INWY * 16; i += NTHREADS) {
        int g  = i / INWY;           // column group 0..15
        int r  = i - g * INWY;       // row 0..33 (consecutive lanes -> consecutive rows)
        int c0 = g << 1;
        const f2_t*  pab = sAB + r * PAB + c0;
        const float* pf  = sF + r * PF + c0;

        f2_t aAB[2]   = {0, 0};
        f2_t aAABB[2] = {0, 0};
        f2_t aAFBF[2] = {0, 0};
        f2_t aFFF[2]  = {0, 0};

        #pragma unroll
        for (int ii = 0; ii < 12; ii++) {
            f2_t  ab = pab[ii];
            float fv = pf[ii];
            f2_t ffp  = pack2(fv, fv);
            f2_t fff  = pack2(fv, fv * fv);
            f2_t aabb = mul2(ab, ab);
            f2_t afbf = mul2(ab, ffp);
            #pragma unroll
            for (int j = 0; j < 2; j++) {
                int k = ii - j;
                if (k >= 0 && k < WIN) {
                    fma2(aAB[j],   GSYM(k), ab);
                    fma2(aAABB[j], GSYM(k), aabb);
                    fma2(aAFBF[j], GSYM(k), afbf);
                    fma2(aFFF[j],  GSYM(k), fff);
                }
            }
        }
        ulonglong2* prow = hb + r * PHB + c0;
        #pragma unroll
        for (int j = 0; j < 2; j++) {
            prow[j]          = make_ulonglong2(aAB[j],   aAABB[j]);
            prow[HB1OFF + j] = make_ulonglong2(aAFBF[j], aFFF[j]);
        }
    }
    __syncthreads();

    // ---- vertical pass: field-split, thread = 1 col x 6 rows x half fields ----
    // 4 row-groups x 6 rows = 24 = TSY exactly. bg = (vc + 4*half) mod 8 -> CF.
    const int half = tid & 1;
    const int vc   = (tid >> 1) & 31;
    const int r0   = (tid >> 6) * 6;   // 0,6,12,18

    const ulonglong2* base = hb + half * HB1OFF + vc;

    f2_t vX[6], vY[6];
    #pragma unroll
    for (int j = 0; j < 6; j++) { vX[j] = 0; vY[j] = 0; }

    #pragma unroll
    for (int ii = 0; ii < 16; ii++) {
        ulonglong2 h = base[(r0 + ii) * PHB];   // max row 18+15=33 ✓
        #pragma unroll
        for (int j = 0; j < 6; j++) {
            int k = ii - j;
            if (k >= 0 && k < WIN) {
                fma2(vX[j], GSYM(k), h.x);
                fma2(vY[j], GSYM(k), h.y);
            }
        }
    }

    // ---- 3 exchange rounds; even lane handles px e, odd px e+3 ----
    float local = 0.f;
    const int gy_base = blockIdx.y * TSY + r0;
    #pragma unroll
    for (int e = 0; e < 3; e++) {
        f2_t sX = half ? vX[e] : vX[e + 3];
        f2_t sY = half ? vY[e] : vY[e + 3];
        f2_t rX = __shfl_xor_sync(0xffffffffu, sX, 1);
        f2_t rY = __shfl_xor_sync(0xffffffffu, sY, 1);
        int j = half ? e + 3 : e;
        if (gy_base + j < 512) {
            float muA, muB, eAA, eBB, eAF, eBF, muF, eFF;
            if (half) {   // own = (AFBF, FFF); recv = (AB, AABB)
                unpack2(rX,    muA, muB);
                unpack2(rY,    eAA, eBB);
                unpack2(vX[j], eAF, eBF);
                unpack2(vY[j], muF, eFF);
            } else {      // own = (AB, AABB); recv = (AFBF, FFF)
                unpack2(vX[j], muA, muB);
                unpack2(vY[j], eAA, eBB);
                unpack2(rX,    eAF, eBF);
                unpack2(rY,    muF, eFF);
            }
            local += ssim_val(muA, muF, eAA, eFF, eAF);
            local += ssim_val(muB, muF, eBB, eFF, eBF);
        }
    }

    // ---- block reduction ----
    #pragma unroll
    for (int o = 16; o > 0; o >>= 1)
        local += __shfl_down_sync(0xffffffffu, local, o);
    if ((tid & 31) == 0) red[tid >> 5] = local;
    __syncthreads();

    const int bid = blockIdx.x + 16 * blockIdx.y + (16 * GRIDY) * blockIdx.z;
    __shared__ bool is_last;
    if (tid == 0) {
        float v = 0.f;
        #pragma unroll
        for (int w = 0; w < 8; w++) v += red[w];
        g_partials[bid] = v;
        __threadfence();
        unsigned int old = atomicAdd(&g_done, 1u);
        is_last = (old == NBLOCKS - 1);
    }
    __syncthreads();

    if (is_last) {
        double s = 0.0;
        for (int i = tid; i < NBLOCKS; i += NTHREADS)
            s += (double)__ldcg(&g_partials[i]);
        #pragma unroll
        for (int o = 16; o > 0; o >>= 1)
            s += __shfl_down_sync(0xffffffffu, s, o);
        double* redd = (double*)red;
        if ((tid & 31) == 0) redd[tid >> 5] = s;
        __syncthreads();
        if (tid == 0) {
            double t = 0.0;
            #pragma unroll
            for (int w = 0; w < 8; w++) t += redd[w];
            out[0] = (float)(0.5 * t / 12582912.0);
            g_done = 0;
        }
    }
}

extern "C" void kernel_launch(void* const* d_in, const int* in_sizes, int n_in,
                              void* d_out, int out_size) {
    const float* A = (const float*)d_in[0];
    const float* B = (const float*)d_in[1];
    const float* F = (const float*)d_in[2];

    GW gw;
    double gd[WIN], s = 0.0;
    for (int i = 0; i < WIN; i++) {
        double d = (double)(i - RAD);
        gd[i] = exp(-(d * d) / (2.0 * 1.5 * 1.5));
        s += gd[i];
    }
    for (int i = 0; i < WIN; i++) gw.g[i] = (float)(gd[i] / s);

    cudaFuncSetAttribute(ssim_tile_kernel,
                         cudaFuncAttributeMaxDynamicSharedMemorySize, SMEM_BYTES);

    dim3 grid(512 / TSX, GRIDY, 16 * 3);
    ssim_tile_kernel<<<grid, NTHREADS, SMEM_BYTES>>>(A, B, F, gw, (float*)d_out);
}

// round 14
// speedup vs baseline: 1.0920x; 1.0920x over previous
#include <cuda_runtime.h>
#include <math.h>

#define WIN   11
#define RAD   5
#define TSX   32
#define TSY   48
#define INWX  42              // TSX + 2*RAD
#define INWY  58              // TSY + 2*RAD
#define PP    43              // raw pitch in 16B units (odd -> CF row-walk LDS.128)
#define PHB   33              // hb pitch in ull2 units (odd -> CF stores + v-loads)
#define NTHREADS 512
#define GRIDY 11              // ceil(512/48)
#define NBLOCKS  (16 * GRIDY * 48)

#define C1 0.0001f
#define C2 0.0009f

struct GW { float g[WIN]; };

typedef unsigned long long f2_t;
__device__ __forceinline__ f2_t pack2(float lo, float hi) {
    f2_t r; asm("mov.b64 %0, {%1, %2};" : "=l"(r) : "f"(lo), "f"(hi)); return r;
}
__device__ __forceinline__ void unpack2(f2_t v, float& lo, float& hi) {
    asm("mov.b64 {%0, %1}, %2;" : "=f"(lo), "=f"(hi) : "l"(v));
}
__device__ __forceinline__ void fma2(f2_t& d, f2_t a, f2_t b) {
    asm("fma.rn.f32x2 %0, %1, %2, %0;" : "+l"(d) : "l"(a), "l"(b));
}
__device__ __forceinline__ f2_t mul2(f2_t a, f2_t b) {
    f2_t r; asm("mul.rn.f32x2 %0, %1, %2;" : "=l"(r) : "l"(a), "l"(b)); return r;
}

__device__ float        g_partials[NBLOCKS];
__device__ unsigned int g_done = 0;

// ---- shared layout (float units) ----
// sP  : ull2[58][43]  per px: (AB, FF2)   = 9976 floats (39.9KB)
// hb0 : ull2[58][33]  (AB, AABB)          = 7656 floats (30.6KB)
// hb1 : ull2[58][33]  (AFBF, FFF)         = 7656 floats (30.6KB)
#define OFF_HB0  9976
#define OFF_HB1  (OFF_HB0 + 7656)
#define OFF_RED  (OFF_HB1 + 7656)
#define SMEM_FLOATS (OFF_RED + 24)
#define SMEM_BYTES  (SMEM_FLOATS * 4)   // ~101.3KB -> 2 CTAs/SM (202.6/228KB)

__device__ __forceinline__ float ssim_val(float mu1, float mu2,
                                          float e11, float e22, float e12) {
    float mu1sq = mu1 * mu1;
    float mu2sq = mu2 * mu2;
    float mu12  = mu1 * mu2;
    float num = (2.0f * mu12 + C1) * (2.0f * (e12 - mu12) + C2);
    float den = (mu1sq + mu2sq + C1) * ((e11 - mu1sq) + (e22 - mu2sq) + C2);
    return __fdividef(num, den);
}

// symmetric taps: g[k] == g[10-k]; k compile-time at every use
#define GSYM(k) gg[(k) < 6 ? (k) : 10 - (k)]

__global__ __launch_bounds__(NTHREADS, 2)
void ssim_tile_kernel(const float* __restrict__ A,
                      const float* __restrict__ B,
                      const float* __restrict__ F,
                      GW gw,
                      float* __restrict__ out) {
    extern __shared__ float sm[];
    ulonglong2* sP  = (ulonglong2*)sm;
    ulonglong2* hb0 = (ulonglong2*)(sm + OFF_HB0);
    ulonglong2* hb1 = (ulonglong2*)(sm + OFF_HB1);
    float*      red = sm + OFF_RED;

    const int tid = threadIdx.x;
    const int x0 = blockIdx.x * TSX - RAD;
    const int y0 = blockIdx.y * TSY - RAD;
    const size_t pbase = (size_t)blockIdx.z * (512 * 512);

    f2_t gg[6];
    #pragma unroll
    for (int k = 0; k < 6; k++) gg[k] = pack2(gw.g[k], gw.g[k]);

    // ---- stage raw: per pixel (A,B)|(F,F^2), zero-padded ----
    for (int i = tid; i < INWY * INWX; i += NTHREADS) {
        int r = i / INWX;
        int c = i - r * INWX;
        int gx = x0 + c, gy = y0 + r;
        float a = 0.f, b = 0.f, f = 0.f;
        if ((unsigned)gx < 512u && (unsigned)gy < 512u) {
            size_t off = pbase + (size_t)gy * 512 + gx;
            a = A[off]; b = B[off]; f = F[off];
        }
        sP[r * PP + c] = make_ulonglong2(pack2(a, b), pack2(f, f * f));
    }
    __syncthreads();

    // ---- horizontal pass: 58 rows x 16 groups = 928 items, lanes walk rows ----
    for (int i = tid; i < INWY * 16; i += NTHREADS) {
        int g  = i / INWY;           // column group 0..15
        int r  = i - g * INWY;       // row 0..57 (consecutive lanes -> consecutive rows)
        int c0 = g << 1;
        const ulonglong2* p = sP + r * PP + c0;

        f2_t aAB[2]   = {0, 0};
        f2_t aAABB[2] = {0, 0};
        f2_t aAFBF[2] = {0, 0};
        f2_t aFFF[2]  = {0, 0};

        #pragma unroll
        for (int ii = 0; ii < 12; ii++) {
            ulonglong2 v = p[ii];
            f2_t ab  = v.x;
            f2_t ff2 = v.y;          // (F, F^2) -- IS the FFF field
            float fl, fh;
            unpack2(ff2, fl, fh);
            f2_t ffp  = pack2(fl, fl);
            f2_t aabb = mul2(ab, ab);
            f2_t afbf = mul2(ab, ffp);
            #pragma unroll
            for (int j = 0; j < 2; j++) {
                int k = ii - j;
                if (k >= 0 && k < WIN) {
                    fma2(aAB[j],   GSYM(k), ab);
                    fma2(aAABB[j], GSYM(k), aabb);
                    fma2(aAFBF[j], GSYM(k), afbf);
                    fma2(aFFF[j],  GSYM(k), ff2);
                }
            }
        }
        int o = r * PHB + c0;
        #pragma unroll
        for (int j = 0; j < 2; j++) {
            hb0[o + j] = make_ulonglong2(aAB[j],   aAABB[j]);
            hb1[o + j] = make_ulonglong2(aAFBF[j], aFFF[j]);
        }
    }
    __syncthreads();

    // ---- vertical pass: 512 threads = 32 cols x 16 groups x 3 rows = 48 ----
    const int vc = tid & 31;
    const int r0 = (tid >> 5) * 3;    // 0,3,...,45; max read row 45+12=57 ✓

    f2_t vAB[3], vAABB[3], vAFBF[3], vFFF[3];
    #pragma unroll
    for (int j = 0; j < 3; j++) { vAB[j]=0; vAABB[j]=0; vAFBF[j]=0; vFFF[j]=0; }

    #pragma unroll
    for (int ii = 0; ii < 13; ii++) {
        int o = (r0 + ii) * PHB + vc;
        ulonglong2 h0 = hb0[o];
        ulonglong2 h1 = hb1[o];
        #pragma unroll
        for (int j = 0; j < 3; j++) {
            int k = ii - j;
            if (k >= 0 && k < WIN) {
                fma2(vAB[j],   GSYM(k), h0.x);
                fma2(vAABB[j], GSYM(k), h0.y);
                fma2(vAFBF[j], GSYM(k), h1.x);
                fma2(vFFF[j],  GSYM(k), h1.y);
            }
        }
    }

    float local = 0.f;
    const int gy_base = blockIdx.y * TSY + r0;
    #pragma unroll
    for (int j = 0; j < 3; j++) {
        if (gy_base + j < 512) {
            float muA, muB, eAA, eBB, eAF, eBF, muF, eFF;
            unpack2(vAB[j],   muA, muB);
            unpack2(vAABB[j], eAA, eBB);
            unpack2(vAFBF[j], eAF, eBF);
            unpack2(vFFF[j],  muF, eFF);
            local += ssim_val(muA, muF, eAA, eFF, eAF);
            local += ssim_val(muB, muF, eBB, eFF, eBF);
        }
    }

    // ---- block reduction (16 warps) ----
    #pragma unroll
    for (int o = 16; o > 0; o >>= 1)
        local += __shfl_down_sync(0xffffffffu, local, o);
    if ((tid & 31) == 0) red[tid >> 5] = local;
    __syncthreads();

    const int bid = blockIdx.x + 16 * blockIdx.y + (16 * GRIDY) * blockIdx.z;
    __shared__ bool is_last;
    if (tid == 0) {
        float v = 0.f;
        #pragma unroll
        for (int w = 0; w < 16; w++) v += red[w];
        g_partials[bid] = v;
        __threadfence();
        unsigned int old = atomicAdd(&g_done, 1u);
        is_last = (old == NBLOCKS - 1);
    }
    __syncthreads();

    if (is_last) {
        double s = 0.0;
        for (int i = tid; i < NBLOCKS; i += NTHREADS)
            s += (double)__ldcg(&g_partials[i]);
        #pragma unroll
        for (int o = 16; o > 0; o >>= 1)
            s += __shfl_down_sync(0xffffffffu, s, o);
        double* redd = (double*)red;
        if ((tid & 31) == 0) redd[tid >> 5] = s;
        __syncthreads();
        if (tid == 0) {
            double t = 0.0;
            #pragma unroll
            for (int w = 0; w < 16; w++) t += redd[w];
            out[0] = (float)(0.5 * t / 12582912.0);
            g_done = 0;
        }
    }
}

extern "C" void kernel_launch(void* const* d_in, const int* in_sizes, int n_in,
                              void* d_out, int out_size) {
    const float* A = (const float*)d_in[0];
    const float* B = (const float*)d_in[1];
    const float* F = (const float*)d_in[2];

    GW gw;
    double gd[WIN], s = 0.0;
    for (int i = 0; i < WIN; i++) {
        double d = (double)(i - RAD);
        gd[i] = exp(-(d * d) / (2.0 * 1.5 * 1.5));
        s += gd[i];
    }
    for (int i = 0; i < WIN; i++) gw.g[i] = (float)(gd[i] / s);

    cudaFuncSetAttribute(ssim_tile_kernel,
                         cudaFuncAttributeMaxDynamicSharedMemorySize, SMEM_BYTES);

    dim3 grid(512 / TSX, GRIDY, 16 * 3);
    ssim_tile_kernel<<<grid, NTHREADS, SMEM_BYTES>>>(A, B, F, gw, (float*)d_out);
}